// round 1
// baseline (speedup 1.0000x reference)
#include <cuda_runtime.h>

#define HH 56
#define WW 56
#define WF 29          // 56/2 + 1
#define BB 32
#define CCH 768
#define NBLK 4
#define SPEC (BB*HH*WF*CCH)   // 39,911,424 floats per buffer
#define SSHRINK 0.01f

typedef unsigned long long ull;

// ---------------- scratch (device globals; no allocation allowed) -------------
__device__ float g_Ar[SPEC];
__device__ float g_Ai[SPEC];
__device__ float g_Br[SPEC];
__device__ float g_Bi[SPEC];

// duplicated ("pair") trig tables for f32x2 math
__device__ float g_cwf_d[WF*WW*2], g_swf_d[WF*WW*2];   // forward rfft along W
__device__ float g_ch_d[HH*HH*2],  g_sh_d[HH*HH*2];    // FFT along H (fwd/inv share)
__device__ float g_cw2_d[WW*WF*2], g_sw2_d[WW*WF*2];   // inverse rfft along W (with 1/2/1 coefs)

// expanded real block-MLP weights: [blk][384][384], plus biases [blk][384]
__device__ float g_W1[NBLK*384*384], g_W2[NBLK*384*384];
__device__ float g_b1[NBLK*384],     g_b2[NBLK*384];

__device__ __forceinline__ void fma2(ull& acc, ull a, ull b){
    asm("fma.rn.f32x2 %0, %1, %2, %0;" : "+l"(acc) : "l"(a), "l"(b));
}

// ---------------- init: tables + expanded weights ----------------------------
__global__ void init_k(const float* __restrict__ w1, const float* __restrict__ b1,
                       const float* __restrict__ w2, const float* __restrict__ b2)
{
    int tid = blockIdx.x*blockDim.x + threadIdx.x;
    int nt  = gridDim.x*blockDim.x;
    const double TW  = 6.283185307179586476925286766559 / 56.0;
    const double INV = 0.13363062095621219234827870598923; // 1/sqrt(56)

    for (int i = tid; i < WF*WW; i += nt) {
        int k = i / WW, w = i % WW;
        int m = (k*w) % 56;
        float c = (float)(cos(TW*m)*INV), s = (float)(sin(TW*m)*INV);
        g_cwf_d[2*i]=c; g_cwf_d[2*i+1]=c;
        g_swf_d[2*i]=s; g_swf_d[2*i+1]=s;
    }
    for (int i = tid; i < HH*HH; i += nt) {
        int k = i / HH, h = i % HH;
        int m = (k*h) % 56;
        float c = (float)(cos(TW*m)*INV), s = (float)(sin(TW*m)*INV);
        g_ch_d[2*i]=c; g_ch_d[2*i+1]=c;
        g_sh_d[2*i]=s; g_sh_d[2*i+1]=s;
    }
    for (int i = tid; i < WW*WF; i += nt) {
        int w = i / WF, k = i % WF;
        int m = (k*w) % 56;
        double a = (k==0 || k==WF-1) ? 1.0 : 2.0;
        float c = (float)(a*cos(TW*m)*INV), s = (float)(a*sin(TW*m)*INV);
        g_cw2_d[2*i]=c; g_cw2_d[2*i+1]=c;
        g_sw2_d[2*i]=s; g_sw2_d[2*i+1]=s;
    }
    // expanded weights: [xr|xi](P,384) x We(384,384) = [hr|hi]
    for (int i = tid; i < NBLK*384*384; i += nt) {
        int blk = i / (384*384);
        int r   = (i / 384) % 384;
        int k   = i % 384;
        int d = (r < 192) ? r : r-192;
        int kk = (k < 192) ? k : k-192;
        float v1, v2;
        if (r < 192) {
            if (k < 192) { v1 =  w1[((0*NBLK+blk)*192+d)*192+kk]; v2 =  w2[((0*NBLK+blk)*192+d)*192+kk]; }
            else         { v1 =  w1[((1*NBLK+blk)*192+d)*192+kk]; v2 =  w2[((1*NBLK+blk)*192+d)*192+kk]; }
        } else {
            if (k < 192) { v1 = -w1[((1*NBLK+blk)*192+d)*192+kk]; v2 = -w2[((1*NBLK+blk)*192+d)*192+kk]; }
            else         { v1 =  w1[((0*NBLK+blk)*192+d)*192+kk]; v2 =  w2[((0*NBLK+blk)*192+d)*192+kk]; }
        }
        g_W1[i] = v1; g_W2[i] = v2;
    }
    for (int i = tid; i < NBLK*384; i += nt) {
        int blk = i / 384, k = i % 384;
        g_b1[i] = (k < 192) ? b1[(0*NBLK+blk)*192 + k] : b1[(1*NBLK+blk)*192 + k-192];
        g_b2[i] = (k < 192) ? b2[(0*NBLK+blk)*192 + k] : b2[(1*NBLK+blk)*192 + k-192];
    }
}

// ---------------- stage 1: rfft along W (x -> A) -----------------------------
// layout A: [(b*56+h)*29 + kf]*768 + c
__global__ void __launch_bounds__(256) rfftW_k(const float* __restrict__ x)
{
    __shared__ float xs[WW*64];
    __shared__ float csd[WF*WW*2];
    __shared__ float snd[WF*WW*2];
    int bh = blockIdx.x;           // b*56+h
    int c0 = blockIdx.y * 64;
    int t  = threadIdx.x;

    for (int i = t; i < WF*WW*2; i += 256) { csd[i]=g_cwf_d[i]; snd[i]=g_swf_d[i]; }
    const float* xp = x + (size_t)bh*WW*CCH + c0;
    for (int i = t; i < WW*64; i += 256) xs[i] = xp[(size_t)(i>>6)*CCH + (i&63)];
    __syncthreads();

    int cp = t & 31;       // channel pair: cc = 2*cp, 2*cp+1
    int kg = t >> 5;       // 8 groups of 4 k-slots (k<29 valid)
    ull ar[4], ai[4];
    #pragma unroll
    for (int j=0;j<4;j++){ ar[j]=0ull; ai[j]=0ull; }

    for (int w = 0; w < WW; w++) {
        ull v = *(const ull*)&xs[w*64 + 2*cp];
        #pragma unroll
        for (int j = 0; j < 4; j++) {
            int k = kg*4 + j;
            if (k < WF) {
                ull c = *(const ull*)&csd[(k*WW+w)*2];
                ull s = *(const ull*)&snd[(k*WW+w)*2];
                fma2(ar[j], v, c);
                fma2(ai[j], v, s);   // Xi = -sum -> negate at write
            }
        }
    }
    size_t base = (size_t)bh*WF*CCH + c0 + 2*cp;
    #pragma unroll
    for (int j = 0; j < 4; j++) {
        int k = kg*4 + j;
        if (k < WF) {
            float2 r  = *(float2*)&ar[j];
            float2 im = *(float2*)&ai[j];
            float2 in = make_float2(-im.x, -im.y);
            *(float2*)&g_Ar[base + (size_t)k*CCH] = r;
            *(float2*)&g_Ai[base + (size_t)k*CCH] = in;
        }
    }
}

// ---------------- stage 2/5: complex FFT along H -----------------------------
// DIR=0: forward  (A -> B), DIR=1: inverse (B -> A)
#define FFTH_SMEM_FLOATS (2*HH*64 + 2*HH*HH*2)
#define FFTH_SMEM_BYTES  (FFTH_SMEM_FLOATS*4)

template<int DIR>
__global__ void __launch_bounds__(256) fftH_k()
{
    extern __shared__ float sm[];
    float* xr  = sm;
    float* xi  = sm + HH*64;
    float* csd = sm + 2*HH*64;
    float* snd = csd + HH*HH*2;

    int bwf = blockIdx.x;
    int b = bwf / WF, wf = bwf % WF;
    int c0 = blockIdx.y * 64;
    int t  = threadIdx.x;

    const float* inR  = (DIR==0) ? g_Ar : g_Br;
    const float* inI  = (DIR==0) ? g_Ai : g_Bi;
    float*       outR = (DIR==0) ? g_Br : g_Ar;
    float*       outI = (DIR==0) ? g_Bi : g_Ai;

    for (int i = t; i < HH*HH*2; i += 256) { csd[i]=g_ch_d[i]; snd[i]=g_sh_d[i]; }
    for (int i = t; i < HH*64; i += 256) {
        int h = i >> 6, cc = i & 63;
        size_t idx = ((size_t)(b*HH+h)*WF + wf)*CCH + c0 + cc;
        xr[i] = inR[idx]; xi[i] = inI[idx];
    }
    __syncthreads();

    int cp = t & 31;
    int kg = t >> 5;   // 8 groups of 7 -> covers 56 outputs
    // fwd: yr = sum(r*c + i*s) [accA];  yi = sum(i*c) - sum(r*s)  [accB-accC]
    // inv: yi = sum(i*c + r*s) [accA];  yr = sum(r*c) - sum(i*s)  [accB-accC]
    ull accA[7], accB[7], accC[7];
    #pragma unroll
    for (int j=0;j<7;j++){ accA[j]=0ull; accB[j]=0ull; accC[j]=0ull; }

    for (int h = 0; h < HH; h++) {
        ull r  = *(const ull*)&xr[h*64 + 2*cp];
        ull im = *(const ull*)&xi[h*64 + 2*cp];
        #pragma unroll
        for (int j = 0; j < 7; j++) {
            int k = kg*7 + j;
            ull c = *(const ull*)&csd[(k*HH+h)*2];
            ull s = *(const ull*)&snd[(k*HH+h)*2];
            if (DIR == 0) {
                fma2(accA[j], r,  c); fma2(accA[j], im, s);
                fma2(accB[j], im, c); fma2(accC[j], r,  s);
            } else {
                fma2(accA[j], im, c); fma2(accA[j], r,  s);
                fma2(accB[j], r,  c); fma2(accC[j], im, s);
            }
        }
    }
    #pragma unroll
    for (int j = 0; j < 7; j++) {
        int k = kg*7 + j;
        size_t o = ((size_t)(b*HH+k)*WF + wf)*CCH + c0 + 2*cp;
        float2 A  = *(float2*)&accA[j];
        float2 Bv = *(float2*)&accB[j];
        float2 Cv = *(float2*)&accC[j];
        float2 D  = make_float2(Bv.x - Cv.x, Bv.y - Cv.y);
        if (DIR == 0) { *(float2*)&outR[o] = A; *(float2*)&outI[o] = D; }
        else          { *(float2*)&outR[o] = D; *(float2*)&outI[o] = A; }
    }
}

// ---------------- MLP GEMM: (P=51968 x 384) x (384 x 384) per block ----------
// LAYER=1: in B, W1, +bias, relu -> A.  LAYER=2: in A, W2, +bias, softshrink -> B.
template<int LAYER>
__global__ void __launch_bounds__(256) gemm_k()
{
    __shared__ float As[16][264];   // duplicated pairs: value p at [2p],[2p+1]; 256 data + 8 pad
    __shared__ float Bs[16][132];

    int t  = threadIdx.x;
    int tx = t & 15, ty = t >> 4;
    int p0 = blockIdx.x * 128;
    int k0 = blockIdx.y * 128;
    int blk = blockIdx.z;

    const float* inR  = (LAYER==1) ? g_Br : g_Ar;
    const float* inI  = (LAYER==1) ? g_Bi : g_Ai;
    float*       outR = (LAYER==1) ? g_Ar : g_Br;
    float*       outI = (LAYER==1) ? g_Ai : g_Bi;
    const float* Wm   = ((LAYER==1) ? g_W1 : g_W2) + (size_t)blk*384*384;
    const float* bias = ((LAYER==1) ? g_b1 : g_b2) + blk*384;

    ull acc[8][4];
    #pragma unroll
    for (int i=0;i<8;i++)
        #pragma unroll
        for (int j=0;j<4;j++) acc[i][j]=0ull;

    for (int kc = 0; kc < 24; kc++) {
        int d0 = kc * 16;
        const float* src = (d0 < 192) ? inR : inI;
        size_t soff = (size_t)blk*192 + (size_t)((d0 < 192) ? d0 : d0-192);
        __syncthreads();
        #pragma unroll
        for (int l = 0; l < 2; l++) {
            int f = t*2 + l, row = f >> 2, c4 = f & 3;
            float4 v = *(const float4*)&src[(size_t)(p0+row)*CCH + soff + c4*4];
            As[c4*4+0][2*row] = v.x; As[c4*4+0][2*row+1] = v.x;
            As[c4*4+1][2*row] = v.y; As[c4*4+1][2*row+1] = v.y;
            As[c4*4+2][2*row] = v.z; As[c4*4+2][2*row+1] = v.z;
            As[c4*4+3][2*row] = v.w; As[c4*4+3][2*row+1] = v.w;
        }
        #pragma unroll
        for (int l = 0; l < 2; l++) {
            int f = t*2 + l, row = f >> 5, c4 = f & 31;
            *(float4*)&Bs[row][c4*4] = *(const float4*)&Wm[(size_t)(d0+row)*384 + k0 + c4*4];
        }
        __syncthreads();
        #pragma unroll
        for (int dd = 0; dd < 16; dd++) {
            ulonglong2 a01 = *(ulonglong2*)&As[dd][8*ty];
            ulonglong2 a23 = *(ulonglong2*)&As[dd][8*ty + 4];
            ulonglong2 a45 = *(ulonglong2*)&As[dd][128 + 8*ty];
            ulonglong2 a67 = *(ulonglong2*)&As[dd][128 + 8*ty + 4];
            ulonglong2 b01 = *(ulonglong2*)&Bs[dd][4*tx];
            ulonglong2 b23 = *(ulonglong2*)&Bs[dd][64 + 4*tx];
            ull a[8] = {a01.x, a01.y, a23.x, a23.y, a45.x, a45.y, a67.x, a67.y};
            ull bb[4] = {b01.x, b01.y, b23.x, b23.y};
            #pragma unroll
            for (int i = 0; i < 8; i++)
                #pragma unroll
                for (int jp = 0; jp < 4; jp++)
                    fma2(acc[i][jp], a[i], bb[jp]);
        }
    }

    #pragma unroll
    for (int i = 0; i < 8; i++) {
        int p = p0 + ((i < 4) ? (ty*4 + i) : (64 + ty*4 + i - 4));
        size_t prow = (size_t)p*CCH + (size_t)blk*192;
        #pragma unroll
        for (int jp = 0; jp < 4; jp++) {
            float2 v = *(float2*)&acc[i][jp];
            int kk = (jp < 2) ? (4*tx + 2*jp) : (64 + 4*tx + 2*(jp-2));
            #pragma unroll
            for (int e = 0; e < 2; e++) {
                int k = k0 + kk + e;
                float val = (e ? v.y : v.x) + bias[k];
                if (LAYER == 1) {
                    val = fmaxf(val, 0.0f);
                } else {
                    val = (val >  SSHRINK) ? val - SSHRINK :
                          ((val < -SSHRINK) ? val + SSHRINK : 0.0f);
                }
                float* dst = (k < 192) ? outR : outI;
                int kr = (k < 192) ? k : k - 192;
                dst[prow + kr] = val;
            }
        }
    }
}

// ---------------- stage 6: inverse rfft along W (A -> out) -------------------
__global__ void __launch_bounds__(256) irfftW_k(float* __restrict__ out)
{
    __shared__ float xr[WF*64], xi[WF*64];
    __shared__ float csd[WW*WF*2], snd[WW*WF*2];
    int bh = blockIdx.x;
    int c0 = blockIdx.y * 64;
    int t  = threadIdx.x;

    for (int i = t; i < WW*WF*2; i += 256) { csd[i]=g_cw2_d[i]; snd[i]=g_sw2_d[i]; }
    for (int i = t; i < WF*64; i += 256) {
        int k = i >> 6, cc = i & 63;
        size_t idx = ((size_t)bh*WF + k)*CCH + c0 + cc;
        xr[i] = g_Ar[idx]; xi[i] = g_Ai[idx];
    }
    __syncthreads();

    int cp = t & 31;
    int kg = t >> 5;   // 8 groups of 7 -> w in 0..55
    ull accP[7], accN[7];
    #pragma unroll
    for (int j=0;j<7;j++){ accP[j]=0ull; accN[j]=0ull; }

    for (int k = 0; k < WF; k++) {
        ull r  = *(const ull*)&xr[k*64 + 2*cp];
        ull im = *(const ull*)&xi[k*64 + 2*cp];
        #pragma unroll
        for (int j = 0; j < 7; j++) {
            int w = kg*7 + j;
            ull c = *(const ull*)&csd[(w*WF+k)*2];
            ull s = *(const ull*)&snd[(w*WF+k)*2];
            fma2(accP[j], r,  c);
            fma2(accN[j], im, s);
        }
    }
    #pragma unroll
    for (int j = 0; j < 7; j++) {
        int w = kg*7 + j;
        float2 P = *(float2*)&accP[j];
        float2 N = *(float2*)&accN[j];
        float2 o = make_float2(P.x - N.x, P.y - N.y);
        *(float2*)&out[((size_t)bh*WW + w)*CCH + c0 + 2*cp] = o;
    }
}

// ---------------- launch ------------------------------------------------------
extern "C" void kernel_launch(void* const* d_in, const int* in_sizes, int n_in,
                              void* d_out, int out_size)
{
    const float* x  = (const float*)d_in[0];
    const float* w1 = (const float*)d_in[1];
    const float* b1 = (const float*)d_in[2];
    const float* w2 = (const float*)d_in[3];
    const float* b2 = (const float*)d_in[4];
    float* out = (float*)d_out;

    cudaFuncSetAttribute((const void*)fftH_k<0>, cudaFuncAttributeMaxDynamicSharedMemorySize, FFTH_SMEM_BYTES);
    cudaFuncSetAttribute((const void*)fftH_k<1>, cudaFuncAttributeMaxDynamicSharedMemorySize, FFTH_SMEM_BYTES);

    init_k<<<512, 256>>>(w1, b1, w2, b2);
    rfftW_k<<<dim3(BB*HH, 12), 256>>>(x);
    fftH_k<0><<<dim3(BB*WF, 12), 256, FFTH_SMEM_BYTES>>>();
    gemm_k<1><<<dim3(406, 3, NBLK), 256>>>();
    gemm_k<2><<<dim3(406, 3, NBLK), 256>>>();
    fftH_k<1><<<dim3(BB*WF, 12), 256, FFTH_SMEM_BYTES>>>();
    irfftW_k<<<dim3(BB*HH, 12), 256>>>(out);
}

// round 3
// speedup vs baseline: 1.9126x; 1.9126x over previous
#include <cuda_runtime.h>
#include <cstdint>

#define HH 56
#define WW 56
#define WF 29          // 56/2 + 1
#define BB 32
#define CCH 768
#define NBLK 4
#define SPEC (BB*HH*WF*CCH)
#define SSHRINK 0.01f

typedef unsigned long long ull;

// ---------------- scratch (device globals; no allocation allowed) -------------
__device__ float g_Ar[SPEC];
__device__ float g_Ai[SPEC];
__device__ float g_Br[SPEC];
__device__ float g_Bi[SPEC];

__device__ float g_cwf_d[WF*WW*2], g_swf_d[WF*WW*2];
__device__ float g_ch_d[HH*HH*2],  g_sh_d[HH*HH*2];
__device__ float g_cw2_d[WW*WF*2], g_sw2_d[WW*WF*2];

// TRANSPOSED expanded weights (B[n][k] = W[k][n]), tf32-rounded: [blk][384][384]
__device__ float g_W1[NBLK*384*384], g_W2[NBLK*384*384];
__device__ float g_b1[NBLK*384],     g_b2[NBLK*384];

__device__ __forceinline__ void fma2(ull& acc, ull a, ull b){
    asm("fma.rn.f32x2 %0, %1, %2, %0;" : "+l"(acc) : "l"(a), "l"(b));
}
__device__ __forceinline__ float to_tf32(float x){
    uint32_t u; asm("cvt.rna.tf32.f32 %0, %1;" : "=r"(u) : "f"(x));
    return __uint_as_float(u);
}
__device__ __forceinline__ uint32_t smem_u32(const void* p) {
    uint32_t a;
    asm("{ .reg .u64 t; cvta.to.shared.u64 t, %1; cvt.u32.u64 %0, t; }" : "=r"(a) : "l"(p));
    return a;
}
#define CP_ASYNC16(sa, gp) \
    asm volatile("cp.async.cg.shared.global [%0], [%1], 16;" :: "r"(sa), "l"(gp))
#define CP_COMMIT() asm volatile("cp.async.commit_group;" ::: "memory")
#define CP_WAIT(n)  asm volatile("cp.async.wait_group %0;" :: "n"(n) : "memory")

__device__ __forceinline__ void mma1688(float c[4], const uint32_t a[4], uint32_t b0, uint32_t b1){
    asm volatile("mma.sync.aligned.m16n8k8.row.col.f32.tf32.tf32.f32 "
        "{%0,%1,%2,%3}, {%4,%5,%6,%7}, {%8,%9}, {%0,%1,%2,%3};"
        : "+f"(c[0]), "+f"(c[1]), "+f"(c[2]), "+f"(c[3])
        : "r"(a[0]), "r"(a[1]), "r"(a[2]), "r"(a[3]), "r"(b0), "r"(b1));
}

// ---------------- init: tables + transposed tf32 weights ---------------------
__global__ void init_k(const float* __restrict__ w1, const float* __restrict__ b1,
                       const float* __restrict__ w2, const float* __restrict__ b2)
{
    int tid = blockIdx.x*blockDim.x + threadIdx.x;
    int nt  = gridDim.x*blockDim.x;
    const double TW  = 6.283185307179586476925286766559 / 56.0;
    const double INV = 0.13363062095621219234827870598923; // 1/sqrt(56)

    for (int i = tid; i < WF*WW; i += nt) {
        int k = i / WW, w = i % WW;
        int m = (k*w) % 56;
        float c = (float)(cos(TW*m)*INV), s = (float)(sin(TW*m)*INV);
        g_cwf_d[2*i]=c; g_cwf_d[2*i+1]=c;
        g_swf_d[2*i]=s; g_swf_d[2*i+1]=s;
    }
    for (int i = tid; i < HH*HH; i += nt) {
        int k = i / HH, h = i % HH;
        int m = (k*h) % 56;
        float c = (float)(cos(TW*m)*INV), s = (float)(sin(TW*m)*INV);
        g_ch_d[2*i]=c; g_ch_d[2*i+1]=c;
        g_sh_d[2*i]=s; g_sh_d[2*i+1]=s;
    }
    for (int i = tid; i < WW*WF; i += nt) {
        int w = i / WF, k = i % WF;
        int m = (k*w) % 56;
        double a = (k==0 || k==WF-1) ? 1.0 : 2.0;
        float c = (float)(a*cos(TW*m)*INV), s = (float)(a*sin(TW*m)*INV);
        g_cw2_d[2*i]=c; g_cw2_d[2*i+1]=c;
        g_sw2_d[2*i]=s; g_sw2_d[2*i+1]=s;
    }
    // g_W[blk][n][kd] = W_expanded[kd][n], rounded to tf32
    for (int i = tid; i < NBLK*384*384; i += nt) {
        int blk = i / (384*384);
        int n   = (i / 384) % 384;
        int kd  = i % 384;
        int r = kd, k = n;
        int d  = (r < 192) ? r : r-192;
        int kk = (k < 192) ? k : k-192;
        float v1, v2;
        if (r < 192) {
            if (k < 192) { v1 =  w1[((0*NBLK+blk)*192+d)*192+kk]; v2 =  w2[((0*NBLK+blk)*192+d)*192+kk]; }
            else         { v1 =  w1[((1*NBLK+blk)*192+d)*192+kk]; v2 =  w2[((1*NBLK+blk)*192+d)*192+kk]; }
        } else {
            if (k < 192) { v1 = -w1[((1*NBLK+blk)*192+d)*192+kk]; v2 = -w2[((1*NBLK+blk)*192+d)*192+kk]; }
            else         { v1 =  w1[((0*NBLK+blk)*192+d)*192+kk]; v2 =  w2[((0*NBLK+blk)*192+d)*192+kk]; }
        }
        g_W1[i] = to_tf32(v1); g_W2[i] = to_tf32(v2);
    }
    for (int i = tid; i < NBLK*384; i += nt) {
        int blk = i / 384, k = i % 384;
        g_b1[i] = (k < 192) ? b1[(0*NBLK+blk)*192 + k] : b1[(1*NBLK+blk)*192 + k-192];
        g_b2[i] = (k < 192) ? b2[(0*NBLK+blk)*192 + k] : b2[(1*NBLK+blk)*192 + k-192];
    }
}

// ---------------- stage 1: rfft along W (x -> A) -----------------------------
__global__ void __launch_bounds__(256) rfftW_k(const float* __restrict__ x)
{
    __shared__ float xs[WW*64];
    __shared__ float csd[WF*WW*2];
    __shared__ float snd[WF*WW*2];
    int bh = blockIdx.x;
    int c0 = blockIdx.y * 64;
    int t  = threadIdx.x;

    for (int i = t; i < WF*WW*2; i += 256) { csd[i]=g_cwf_d[i]; snd[i]=g_swf_d[i]; }
    const float* xp = x + (size_t)bh*WW*CCH + c0;
    for (int i = t; i < WW*64; i += 256) xs[i] = xp[(size_t)(i>>6)*CCH + (i&63)];
    __syncthreads();

    int cp = t & 31;
    int kg = t >> 5;
    ull ar[4], ai[4];
    #pragma unroll
    for (int j=0;j<4;j++){ ar[j]=0ull; ai[j]=0ull; }

    for (int w = 0; w < WW; w++) {
        ull v = *(const ull*)&xs[w*64 + 2*cp];
        #pragma unroll
        for (int j = 0; j < 4; j++) {
            int k = kg*4 + j;
            if (k < WF) {
                ull c = *(const ull*)&csd[(k*WW+w)*2];
                ull s = *(const ull*)&snd[(k*WW+w)*2];
                fma2(ar[j], v, c);
                fma2(ai[j], v, s);
            }
        }
    }
    size_t base = (size_t)bh*WF*CCH + c0 + 2*cp;
    #pragma unroll
    for (int j = 0; j < 4; j++) {
        int k = kg*4 + j;
        if (k < WF) {
            float2 r  = *(float2*)&ar[j];
            float2 im = *(float2*)&ai[j];
            float2 in = make_float2(-im.x, -im.y);
            *(float2*)&g_Ar[base + (size_t)k*CCH] = r;
            *(float2*)&g_Ai[base + (size_t)k*CCH] = in;
        }
    }
}

// ---------------- stage 2/5: complex FFT along H -----------------------------
#define FFTH_SMEM_FLOATS (2*HH*64 + 2*HH*HH*2)
#define FFTH_SMEM_BYTES  (FFTH_SMEM_FLOATS*4)

template<int DIR>
__global__ void __launch_bounds__(256) fftH_k()
{
    extern __shared__ float sm[];
    float* xr  = sm;
    float* xi  = sm + HH*64;
    float* csd = sm + 2*HH*64;
    float* snd = csd + HH*HH*2;

    int bwf = blockIdx.x;
    int b = bwf / WF, wf = bwf % WF;
    int c0 = blockIdx.y * 64;
    int t  = threadIdx.x;

    const float* inR  = (DIR==0) ? g_Ar : g_Br;
    const float* inI  = (DIR==0) ? g_Ai : g_Bi;
    float*       outR = (DIR==0) ? g_Br : g_Ar;
    float*       outI = (DIR==0) ? g_Bi : g_Ai;

    for (int i = t; i < HH*HH*2; i += 256) { csd[i]=g_ch_d[i]; snd[i]=g_sh_d[i]; }
    for (int i = t; i < HH*64; i += 256) {
        int h = i >> 6, cc = i & 63;
        size_t idx = ((size_t)(b*HH+h)*WF + wf)*CCH + c0 + cc;
        xr[i] = inR[idx]; xi[i] = inI[idx];
    }
    __syncthreads();

    int cp = t & 31;
    int kg = t >> 5;
    ull accA[7], accB[7], accC[7];
    #pragma unroll
    for (int j=0;j<7;j++){ accA[j]=0ull; accB[j]=0ull; accC[j]=0ull; }

    for (int h = 0; h < HH; h++) {
        ull r  = *(const ull*)&xr[h*64 + 2*cp];
        ull im = *(const ull*)&xi[h*64 + 2*cp];
        #pragma unroll
        for (int j = 0; j < 7; j++) {
            int k = kg*7 + j;
            ull c = *(const ull*)&csd[(k*HH+h)*2];
            ull s = *(const ull*)&snd[(k*HH+h)*2];
            if (DIR == 0) {
                fma2(accA[j], r,  c); fma2(accA[j], im, s);
                fma2(accB[j], im, c); fma2(accC[j], r,  s);
            } else {
                fma2(accA[j], im, c); fma2(accA[j], r,  s);
                fma2(accB[j], r,  c); fma2(accC[j], im, s);
            }
        }
    }
    #pragma unroll
    for (int j = 0; j < 7; j++) {
        int k = kg*7 + j;
        size_t o = ((size_t)(b*HH+k)*WF + wf)*CCH + c0 + 2*cp;
        float2 A  = *(float2*)&accA[j];
        float2 Bv = *(float2*)&accB[j];
        float2 Cv = *(float2*)&accC[j];
        float2 D  = make_float2(Bv.x - Cv.x, Bv.y - Cv.y);
        if (DIR == 0) {
            // outputs feed the tf32 GEMM: pre-round
            A.x = to_tf32(A.x); A.y = to_tf32(A.y);
            D.x = to_tf32(D.x); D.y = to_tf32(D.y);
            *(float2*)&outR[o] = A; *(float2*)&outI[o] = D;
        } else {
            *(float2*)&outR[o] = D; *(float2*)&outI[o] = A;
        }
    }
}

// ========== MLP GEMM via mma.sync tf32 =======================================
// out[P,384] = in[P,384] x W[384,384]^T(stored [n][k]) per (layer, blk)
// CTA: 256 thr (8 warps, 4x2), tile M=128 N=128, K chunks of 32, double-buffered
// cp.async. smem stride 36 floats -> conflict-free fragment LDS.
#define GA0 0
#define GA1 4608
#define GB0 9216
#define GB1 13824
#define GBIAS 18432
#define GEMM_SMEM ((18432 + 128)*4)

template<int LAYER>
__device__ __forceinline__ void gload(int blk, int p0, int n0, int kc,
                                      uint32_t aS, uint32_t bS, int t)
{
    const float* inR = (LAYER==1) ? g_Br : g_Ar;
    const float* inI = (LAYER==1) ? g_Bi : g_Ai;
    const float* Wt  = ((LAYER==1) ? g_W1 : g_W2) + (size_t)blk*384*384;
    const float* src = (kc < 6) ? inR : inI;
    int koff = blk*192 + ((kc < 6) ? kc*32 : (kc-6)*32);
    int row = t >> 3, q = t & 7;
    #pragma unroll
    for (int i = 0; i < 4; i++) {
        int r = row + i*32;
        CP_ASYNC16(aS + (uint32_t)(r*36 + q*4)*4, &src[(size_t)(p0+r)*CCH + koff + q*4]);
    }
    int kb = kc*32;
    #pragma unroll
    for (int i = 0; i < 4; i++) {
        int r = row + i*32;
        CP_ASYNC16(bS + (uint32_t)(r*36 + q*4)*4, &Wt[(size_t)(n0+r)*384 + kb + q*4]);
    }
}

template<int LAYER>
__global__ void __launch_bounds__(256, 2) gemmM_k()
{
    extern __shared__ float sm[];
    uint32_t smem_base = smem_u32(sm);
    int t = threadIdx.x;
    int wid = t >> 5, lane = t & 31;
    int g = lane >> 2, tig = lane & 3;
    int warpM = wid & 3, warpN = wid >> 2;
    int p0  = blockIdx.x * 128;
    int n0  = blockIdx.y * 128;
    int blk = blockIdx.z;

    float*       outR = (LAYER==1) ? g_Ar : g_Br;
    float*       outI = (LAYER==1) ? g_Ai : g_Bi;
    const float* bias = ((LAYER==1) ? g_b1 : g_b2) + blk*384;

    for (int i = t; i < 128; i += 256) sm[GBIAS + i] = bias[n0 + i];

    float c[2][8][4];
    #pragma unroll
    for (int mt=0;mt<2;mt++)
        #pragma unroll
        for (int nt=0;nt<8;nt++)
            #pragma unroll
            for (int j=0;j<4;j++) c[mt][nt][j] = 0.f;

    gload<LAYER>(blk, p0, n0, 0, smem_base + GA0*4, smem_base + GB0*4, t);
    CP_COMMIT();

    #pragma unroll 1
    for (int kc = 0; kc < 12; kc++) {
        int b = kc & 1;
        if (kc + 1 < 12) {
            gload<LAYER>(blk, p0, n0, kc+1,
                         smem_base + (b ? GA0 : GA1)*4,
                         smem_base + (b ? GB0 : GB1)*4, t);
            CP_COMMIT();
            CP_WAIT(1);
        } else {
            CP_WAIT(0);
        }
        __syncthreads();

        const float* As = sm + (b ? GA1 : GA0);
        const float* Bs = sm + (b ? GB1 : GB0);
        #pragma unroll
        for (int ks = 0; ks < 4; ks++) {
            uint32_t a[2][4];
            #pragma unroll
            for (int mt = 0; mt < 2; mt++) {
                int r = warpM*32 + mt*16 + g;
                int col = ks*8 + tig;
                a[mt][0] = __float_as_uint(As[r*36 + col]);
                a[mt][1] = __float_as_uint(As[(r+8)*36 + col]);
                a[mt][2] = __float_as_uint(As[r*36 + col + 4]);
                a[mt][3] = __float_as_uint(As[(r+8)*36 + col + 4]);
            }
            #pragma unroll
            for (int nt = 0; nt < 8; nt++) {
                int n = warpN*64 + nt*8 + g;
                uint32_t b0 = __float_as_uint(Bs[n*36 + ks*8 + tig]);
                uint32_t b1 = __float_as_uint(Bs[n*36 + ks*8 + tig + 4]);
                mma1688(c[0][nt], a[0], b0, b1);
                mma1688(c[1][nt], a[1], b0, b1);
            }
        }
        __syncthreads();
    }

    // epilogue: bias + activation (+ tf32 round for layer 1), write R/I halves
    #pragma unroll
    for (int mt = 0; mt < 2; mt++) {
        #pragma unroll
        for (int rr = 0; rr < 2; rr++) {
            int r = p0 + warpM*32 + mt*16 + rr*8 + g;
            size_t rowoff = (size_t)r*CCH + blk*192;
            #pragma unroll
            for (int nt = 0; nt < 8; nt++) {
                int kl = warpN*64 + nt*8 + 2*tig;   // 0..127 within tile
                int ko = n0 + kl;                    // 0..383
                float v0 = c[mt][nt][rr*2+0] + sm[GBIAS + kl];
                float v1 = c[mt][nt][rr*2+1] + sm[GBIAS + kl + 1];
                if (LAYER == 1) {
                    v0 = to_tf32(fmaxf(v0, 0.f));
                    v1 = to_tf32(fmaxf(v1, 0.f));
                } else {
                    v0 = (v0 >  SSHRINK) ? v0-SSHRINK : ((v0 < -SSHRINK) ? v0+SSHRINK : 0.f);
                    v1 = (v1 >  SSHRINK) ? v1-SSHRINK : ((v1 < -SSHRINK) ? v1+SSHRINK : 0.f);
                }
                float* dst = (ko < 192) ? outR : outI;
                int kr = (ko < 192) ? ko : ko - 192;
                *(float2*)&dst[rowoff + kr] = make_float2(v0, v1);
            }
        }
    }
}

// ---------------- stage 6: inverse rfft along W (A -> out) -------------------
__global__ void __launch_bounds__(256) irfftW_k(float* __restrict__ out)
{
    __shared__ float xr[WF*64], xi[WF*64];
    __shared__ float csd[WW*WF*2], snd[WW*WF*2];
    int bh = blockIdx.x;
    int c0 = blockIdx.y * 64;
    int t  = threadIdx.x;

    for (int i = t; i < WW*WF*2; i += 256) { csd[i]=g_cw2_d[i]; snd[i]=g_sw2_d[i]; }
    for (int i = t; i < WF*64; i += 256) {
        int k = i >> 6, cc = i & 63;
        size_t idx = ((size_t)bh*WF + k)*CCH + c0 + cc;
        xr[i] = g_Ar[idx]; xi[i] = g_Ai[idx];
    }
    __syncthreads();

    int cp = t & 31;
    int kg = t >> 5;
    ull accP[7], accN[7];
    #pragma unroll
    for (int j=0;j<7;j++){ accP[j]=0ull; accN[j]=0ull; }

    for (int k = 0; k < WF; k++) {
        ull r  = *(const ull*)&xr[k*64 + 2*cp];
        ull im = *(const ull*)&xi[k*64 + 2*cp];
        #pragma unroll
        for (int j = 0; j < 7; j++) {
            int w = kg*7 + j;
            ull c = *(const ull*)&csd[(w*WF+k)*2];
            ull s = *(const ull*)&snd[(w*WF+k)*2];
            fma2(accP[j], r,  c);
            fma2(accN[j], im, s);
        }
    }
    #pragma unroll
    for (int j = 0; j < 7; j++) {
        int w = kg*7 + j;
        float2 P = *(float2*)&accP[j];
        float2 N = *(float2*)&accN[j];
        float2 o = make_float2(P.x - N.x, P.y - N.y);
        *(float2*)&out[((size_t)bh*WW + w)*CCH + c0 + 2*cp] = o;
    }
}

// ---------------- launch ------------------------------------------------------
extern "C" void kernel_launch(void* const* d_in, const int* in_sizes, int n_in,
                              void* d_out, int out_size)
{
    const float* x  = (const float*)d_in[0];
    const float* w1 = (const float*)d_in[1];
    const float* b1 = (const float*)d_in[2];
    const float* w2 = (const float*)d_in[3];
    const float* b2 = (const float*)d_in[4];
    float* out = (float*)d_out;

    cudaFuncSetAttribute((const void*)fftH_k<0>, cudaFuncAttributeMaxDynamicSharedMemorySize, FFTH_SMEM_BYTES);
    cudaFuncSetAttribute((const void*)fftH_k<1>, cudaFuncAttributeMaxDynamicSharedMemorySize, FFTH_SMEM_BYTES);
    cudaFuncSetAttribute((const void*)gemmM_k<1>, cudaFuncAttributeMaxDynamicSharedMemorySize, GEMM_SMEM);
    cudaFuncSetAttribute((const void*)gemmM_k<2>, cudaFuncAttributeMaxDynamicSharedMemorySize, GEMM_SMEM);

    init_k<<<512, 256>>>(w1, b1, w2, b2);
    rfftW_k<<<dim3(BB*HH, 12), 256>>>(x);
    fftH_k<0><<<dim3(BB*WF, 12), 256, FFTH_SMEM_BYTES>>>();
    gemmM_k<1><<<dim3(406, 3, NBLK), 256, GEMM_SMEM>>>();
    gemmM_k<2><<<dim3(406, 3, NBLK), 256, GEMM_SMEM>>>();
    fftH_k<1><<<dim3(BB*WF, 12), 256, FFTH_SMEM_BYTES>>>();
    irfftW_k<<<dim3(BB*HH, 12), 256>>>(out);
}

// round 4
// speedup vs baseline: 3.0276x; 1.5829x over previous
#include <cuda_runtime.h>
#include <cstdint>

#define HH 56
#define WW 56
#define WF 29          // 56/2 + 1
#define BB 32
#define CCH 768
#define NBLK 4
#define SPEC (BB*HH*WF*CCH)
#define SSHRINK 0.01f

typedef unsigned long long ull;

// ---------------- scratch (device globals; no allocation allowed) -------------
__device__ float g_Ar[SPEC];
__device__ float g_Ai[SPEC];
__device__ float g_Br[SPEC];
__device__ float g_Bi[SPEC];

// tf32 DFT matrices (padded to mma tiles, pads = 0)
__device__ float g_Ch[64*64],  g_Sh[64*64];    // H-FFT: [k][h], k,h<56
__device__ float g_Cwf[32*64], g_Swfn[32*64];  // fwd rfft W: [kf][w], kf<29,w<56 (Swfn = -sin)
__device__ float g_Cw2[64*32], g_Sw2n[64*32];  // inv rfft W: [w][k],  w<56,k<29 (1/2/1 weights, Sw2n=-a*sin)

// TRANSPOSED expanded weights (B[n][k] = W[k][n]), tf32-rounded: [blk][384][384]
__device__ float g_W1[NBLK*384*384], g_W2[NBLK*384*384];
__device__ float g_b1[NBLK*384],     g_b2[NBLK*384];

__device__ __forceinline__ float to_tf32(float x){
    uint32_t u; asm("cvt.rna.tf32.f32 %0, %1;" : "=r"(u) : "f"(x));
    return __uint_as_float(u);
}
__device__ __forceinline__ uint32_t smem_u32(const void* p) {
    uint32_t a;
    asm("{ .reg .u64 t; cvta.to.shared.u64 t, %1; cvt.u32.u64 %0, t; }" : "=r"(a) : "l"(p));
    return a;
}
#define CP_ASYNC16(sa, gp) \
    asm volatile("cp.async.cg.shared.global [%0], [%1], 16;" :: "r"(sa), "l"(gp))
#define CP_COMMIT() asm volatile("cp.async.commit_group;" ::: "memory")
#define CP_WAIT(n)  asm volatile("cp.async.wait_group %0;" :: "n"(n) : "memory")

__device__ __forceinline__ void mma1688(float c[4], const uint32_t a[4], uint32_t b0, uint32_t b1){
    asm volatile("mma.sync.aligned.m16n8k8.row.col.f32.tf32.tf32.f32 "
        "{%0,%1,%2,%3}, {%4,%5,%6,%7}, {%8,%9}, {%0,%1,%2,%3};"
        : "+f"(c[0]), "+f"(c[1]), "+f"(c[2]), "+f"(c[3])
        : "r"(a[0]), "r"(a[1]), "r"(a[2]), "r"(a[3]), "r"(b0), "r"(b1));
}

// ---------------- init: tf32 DFT matrices + transposed tf32 weights ----------
__global__ void init_k(const float* __restrict__ w1, const float* __restrict__ b1,
                       const float* __restrict__ w2, const float* __restrict__ b2)
{
    int tid = blockIdx.x*blockDim.x + threadIdx.x;
    int nt  = gridDim.x*blockDim.x;
    const double TW  = 6.283185307179586476925286766559 / 56.0;
    const double INV = 0.13363062095621219234827870598923; // 1/sqrt(56)

    for (int i = tid; i < 64*64; i += nt) {
        int k = i >> 6, h = i & 63;
        float c = 0.f, s = 0.f;
        if (k < 56 && h < 56) {
            int m = (k*h) % 56;
            c = to_tf32((float)(cos(TW*m)*INV));
            s = to_tf32((float)(sin(TW*m)*INV));
        }
        g_Ch[i] = c; g_Sh[i] = s;
    }
    for (int i = tid; i < 32*64; i += nt) {
        int kf = i >> 6, w = i & 63;
        float c = 0.f, s = 0.f;
        if (kf < WF && w < 56) {
            int m = (kf*w) % 56;
            c = to_tf32((float)(cos(TW*m)*INV));
            s = to_tf32((float)(-sin(TW*m)*INV));
        }
        g_Cwf[i] = c; g_Swfn[i] = s;
    }
    for (int i = tid; i < 64*32; i += nt) {
        int w = i >> 5, k = i & 31;
        float c = 0.f, s = 0.f;
        if (w < 56 && k < WF) {
            int m = (k*w) % 56;
            double a = (k==0 || k==WF-1) ? 1.0 : 2.0;
            c = to_tf32((float)(a*cos(TW*m)*INV));
            s = to_tf32((float)(-a*sin(TW*m)*INV));
        }
        g_Cw2[i] = c; g_Sw2n[i] = s;
    }
    // g_W[blk][n][kd] = W_expanded[kd][n], rounded to tf32
    for (int i = tid; i < NBLK*384*384; i += nt) {
        int blk = i / (384*384);
        int n   = (i / 384) % 384;
        int kd  = i % 384;
        int r = kd, k = n;
        int d  = (r < 192) ? r : r-192;
        int kk = (k < 192) ? k : k-192;
        float v1, v2;
        if (r < 192) {
            if (k < 192) { v1 =  w1[((0*NBLK+blk)*192+d)*192+kk]; v2 =  w2[((0*NBLK+blk)*192+d)*192+kk]; }
            else         { v1 =  w1[((1*NBLK+blk)*192+d)*192+kk]; v2 =  w2[((1*NBLK+blk)*192+d)*192+kk]; }
        } else {
            if (k < 192) { v1 = -w1[((1*NBLK+blk)*192+d)*192+kk]; v2 = -w2[((1*NBLK+blk)*192+d)*192+kk]; }
            else         { v1 =  w1[((0*NBLK+blk)*192+d)*192+kk]; v2 =  w2[((0*NBLK+blk)*192+d)*192+kk]; }
        }
        g_W1[i] = to_tf32(v1); g_W2[i] = to_tf32(v2);
    }
    for (int i = tid; i < NBLK*384; i += nt) {
        int blk = i / 384, k = i % 384;
        g_b1[i] = (k < 192) ? b1[(0*NBLK+blk)*192 + k] : b1[(1*NBLK+blk)*192 + k-192];
        g_b2[i] = (k < 192) ? b2[(0*NBLK+blk)*192 + k] : b2[(1*NBLK+blk)*192 + k-192];
    }
}

// ================= stage 1: rfft along W via tensor mma ======================
// per (b,h): out[kf<29, c0+0..127] = Cw * x(56xN),  i-part = Swfn * x
#define RW_C  0
#define RW_S  (32*68)
#define RW_X  (2*32*68)
#define RW_TOT ((2*32*68 + 64*132)*4)

__global__ void __launch_bounds__(256, 2) rfftWT_k(const float* __restrict__ x)
{
    extern __shared__ float sm[];
    float* Cs = sm + RW_C;
    float* Ss = sm + RW_S;
    float* X  = sm + RW_X;
    int bh = blockIdx.x;
    int c0 = blockIdx.y * 128;
    int t  = threadIdx.x;

    for (int i = t; i < 32*64; i += 256) {
        int r = i >> 6, c = i & 63;
        Cs[r*68+c] = g_Cwf[i]; Ss[r*68+c] = g_Swfn[i];
    }
    const float* xp = x + (size_t)bh*WW*CCH + c0;
    for (int i = t; i < 64*32; i += 256) {
        int r = i >> 5, q = i & 31;
        float4 v = make_float4(0.f,0.f,0.f,0.f);
        if (r < 56) v = *(const float4*)&xp[(size_t)r*CCH + q*4];
        v.x = to_tf32(v.x); v.y = to_tf32(v.y); v.z = to_tf32(v.z); v.w = to_tf32(v.w);
        *(float4*)&X[r*132 + q*4] = v;
    }
    __syncthreads();

    int wid = t >> 5, lane = t & 31, g = lane >> 2, tig = lane & 3;
    int warpM = wid & 1, warpN = wid >> 1;   // 2 x 4
    float cr[4][4], ci[4][4];
    #pragma unroll
    for (int nt=0;nt<4;nt++)
        #pragma unroll
        for (int j=0;j<4;j++){ cr[nt][j]=0.f; ci[nt][j]=0.f; }

    #pragma unroll
    for (int ks = 0; ks < 8; ks++) {
        int row = warpM*16 + g, col = ks*8 + tig;
        uint32_t aC[4], aS[4];
        aC[0]=__float_as_uint(Cs[row*68+col]);     aC[1]=__float_as_uint(Cs[(row+8)*68+col]);
        aC[2]=__float_as_uint(Cs[row*68+col+4]);   aC[3]=__float_as_uint(Cs[(row+8)*68+col+4]);
        aS[0]=__float_as_uint(Ss[row*68+col]);     aS[1]=__float_as_uint(Ss[(row+8)*68+col]);
        aS[2]=__float_as_uint(Ss[row*68+col+4]);   aS[3]=__float_as_uint(Ss[(row+8)*68+col+4]);
        #pragma unroll
        for (int nt = 0; nt < 4; nt++) {
            int n = warpN*32 + nt*8 + g;
            uint32_t b0 = __float_as_uint(X[(ks*8+tig)*132 + n]);
            uint32_t b1 = __float_as_uint(X[(ks*8+tig+4)*132 + n]);
            mma1688(cr[nt], aC, b0, b1);
            mma1688(ci[nt], aS, b0, b1);
        }
    }

    size_t ob = (size_t)bh*WF*CCH + c0;
    #pragma unroll
    for (int nt = 0; nt < 4; nt++) {
        int n2 = warpN*32 + nt*8 + 2*tig;
        int k0r = warpM*16 + g, k1r = k0r + 8;
        *(float2*)&g_Ar[ob + (size_t)k0r*CCH + n2] = make_float2(cr[nt][0], cr[nt][1]);
        *(float2*)&g_Ai[ob + (size_t)k0r*CCH + n2] = make_float2(ci[nt][0], ci[nt][1]);
        if (k1r < WF) {
            *(float2*)&g_Ar[ob + (size_t)k1r*CCH + n2] = make_float2(cr[nt][2], cr[nt][3]);
            *(float2*)&g_Ai[ob + (size_t)k1r*CCH + n2] = make_float2(ci[nt][2], ci[nt][3]);
        }
    }
}

// ================= stage 2/5: complex FFT along H via tensor mma =============
// per (b, chunk): columns j = wf*768+c; yr = C xr + sS xi; yi = C xi - sS xr
#define FH_C  0
#define FH_S  (64*68)
#define FH_XR (2*64*68)
#define FH_XI (2*64*68 + 64*132)
#define FH_TOT ((2*64*68 + 2*64*132)*4)
#define HROW (WF*CCH)   // 22272

template<int DIR>
__global__ void __launch_bounds__(256, 2) fftHT_k()
{
    extern __shared__ float sm[];
    float* Cs = sm + FH_C;
    float* Ss = sm + FH_S;
    float* XR = sm + FH_XR;
    float* XI = sm + FH_XI;
    int b  = blockIdx.x;
    int j0 = blockIdx.y * 128;
    int t  = threadIdx.x;

    const float* inR  = (DIR==0) ? g_Ar : g_Br;
    const float* inI  = (DIR==0) ? g_Ai : g_Bi;
    float*       outR = (DIR==0) ? g_Br : g_Ar;
    float*       outI = (DIR==0) ? g_Bi : g_Ai;

    for (int i = t; i < 64*64; i += 256) {
        int r = i >> 6, c = i & 63;
        Cs[r*68+c] = g_Ch[i];
        float s = g_Sh[i];
        Ss[r*68+c] = (DIR==0) ? s : -s;
    }
    size_t base = (size_t)b*HH*HROW + j0;
    for (int i = t; i < 64*32; i += 256) {
        int r = i >> 5, q = i & 31;
        float4 vr = make_float4(0.f,0.f,0.f,0.f), vi = vr;
        if (r < 56) {
            vr = *(const float4*)&inR[base + (size_t)r*HROW + q*4];
            vi = *(const float4*)&inI[base + (size_t)r*HROW + q*4];
        }
        vr.x=to_tf32(vr.x); vr.y=to_tf32(vr.y); vr.z=to_tf32(vr.z); vr.w=to_tf32(vr.w);
        vi.x=to_tf32(vi.x); vi.y=to_tf32(vi.y); vi.z=to_tf32(vi.z); vi.w=to_tf32(vi.w);
        *(float4*)&XR[r*132 + q*4] = vr;
        *(float4*)&XI[r*132 + q*4] = vi;
    }
    __syncthreads();

    int wid = t >> 5, lane = t & 31, g = lane >> 2, tig = lane & 3;
    int warpM = wid & 3, warpN = wid >> 2;   // 4 x 2
    float cr[8][4], ci[8][4];
    #pragma unroll
    for (int nt=0;nt<8;nt++)
        #pragma unroll
        for (int j=0;j<4;j++){ cr[nt][j]=0.f; ci[nt][j]=0.f; }

    #pragma unroll
    for (int ks = 0; ks < 8; ks++) {
        int row = warpM*16 + g, col = ks*8 + tig;
        uint32_t aC[4], aS[4], aSn[4];
        aC[0]=__float_as_uint(Cs[row*68+col]);     aC[1]=__float_as_uint(Cs[(row+8)*68+col]);
        aC[2]=__float_as_uint(Cs[row*68+col+4]);   aC[3]=__float_as_uint(Cs[(row+8)*68+col+4]);
        aS[0]=__float_as_uint(Ss[row*68+col]);     aS[1]=__float_as_uint(Ss[(row+8)*68+col]);
        aS[2]=__float_as_uint(Ss[row*68+col+4]);   aS[3]=__float_as_uint(Ss[(row+8)*68+col+4]);
        #pragma unroll
        for (int j=0;j<4;j++) aSn[j] = aS[j] ^ 0x80000000u;
        #pragma unroll
        for (int nt = 0; nt < 8; nt++) {
            int n = warpN*64 + nt*8 + g;
            uint32_t br0 = __float_as_uint(XR[(ks*8+tig)*132 + n]);
            uint32_t br1 = __float_as_uint(XR[(ks*8+tig+4)*132 + n]);
            uint32_t bi0 = __float_as_uint(XI[(ks*8+tig)*132 + n]);
            uint32_t bi1 = __float_as_uint(XI[(ks*8+tig+4)*132 + n]);
            mma1688(cr[nt], aC,  br0, br1);
            mma1688(cr[nt], aS,  bi0, bi1);
            mma1688(ci[nt], aC,  bi0, bi1);
            mma1688(ci[nt], aSn, br0, br1);
        }
    }

    int k0r = warpM*16 + g;
    #pragma unroll
    for (int nt = 0; nt < 8; nt++) {
        int n2 = warpN*64 + nt*8 + 2*tig;
        float2 r0 = make_float2(cr[nt][0], cr[nt][1]);
        float2 i0 = make_float2(ci[nt][0], ci[nt][1]);
        float2 r1 = make_float2(cr[nt][2], cr[nt][3]);
        float2 i1 = make_float2(ci[nt][2], ci[nt][3]);
        if (DIR == 0) {   // feeds cp.async GEMM: pre-round
            r0.x=to_tf32(r0.x); r0.y=to_tf32(r0.y); i0.x=to_tf32(i0.x); i0.y=to_tf32(i0.y);
            r1.x=to_tf32(r1.x); r1.y=to_tf32(r1.y); i1.x=to_tf32(i1.x); i1.y=to_tf32(i1.y);
        }
        *(float2*)&outR[base + (size_t)k0r*HROW + n2] = r0;
        *(float2*)&outI[base + (size_t)k0r*HROW + n2] = i0;
        if (warpM < 3) {
            *(float2*)&outR[base + (size_t)(k0r+8)*HROW + n2] = r1;
            *(float2*)&outI[base + (size_t)(k0r+8)*HROW + n2] = i1;
        }
    }
}

// ================= stage 6: inverse rfft along W via tensor mma ==============
// per (b,h): out[w<56, c] = Cw2 xr + Sw2n xi
#define IW_C  0
#define IW_S  (64*36)
#define IW_XR (2*64*36)
#define IW_XI (2*64*36 + 32*132)
#define IW_TOT ((2*64*36 + 2*32*132)*4)

__global__ void __launch_bounds__(256, 2) irfftWT_k(float* __restrict__ out)
{
    extern __shared__ float sm[];
    float* Cs = sm + IW_C;
    float* Ss = sm + IW_S;
    float* XR = sm + IW_XR;
    float* XI = sm + IW_XI;
    int bh = blockIdx.x;
    int c0 = blockIdx.y * 128;
    int t  = threadIdx.x;

    for (int i = t; i < 64*32; i += 256) {
        int r = i >> 5, c = i & 31;
        Cs[r*36+c] = g_Cw2[i]; Ss[r*36+c] = g_Sw2n[i];
    }
    size_t base = (size_t)bh*WF*CCH + c0;
    for (int i = t; i < 32*32; i += 256) {
        int r = i >> 5, q = i & 31;
        float4 vr = make_float4(0.f,0.f,0.f,0.f), vi = vr;
        if (r < WF) {
            vr = *(const float4*)&g_Ar[base + (size_t)r*CCH + q*4];
            vi = *(const float4*)&g_Ai[base + (size_t)r*CCH + q*4];
        }
        vr.x=to_tf32(vr.x); vr.y=to_tf32(vr.y); vr.z=to_tf32(vr.z); vr.w=to_tf32(vr.w);
        vi.x=to_tf32(vi.x); vi.y=to_tf32(vi.y); vi.z=to_tf32(vi.z); vi.w=to_tf32(vi.w);
        *(float4*)&XR[r*132 + q*4] = vr;
        *(float4*)&XI[r*132 + q*4] = vi;
    }
    __syncthreads();

    int wid = t >> 5, lane = t & 31, g = lane >> 2, tig = lane & 3;
    int warpM = wid & 3, warpN = wid >> 2;   // 4 x 2
    float co[8][4];
    #pragma unroll
    for (int nt=0;nt<8;nt++)
        #pragma unroll
        for (int j=0;j<4;j++) co[nt][j]=0.f;

    #pragma unroll
    for (int ks = 0; ks < 4; ks++) {
        int row = warpM*16 + g, col = ks*8 + tig;
        uint32_t aC[4], aS[4];
        aC[0]=__float_as_uint(Cs[row*36+col]);     aC[1]=__float_as_uint(Cs[(row+8)*36+col]);
        aC[2]=__float_as_uint(Cs[row*36+col+4]);   aC[3]=__float_as_uint(Cs[(row+8)*36+col+4]);
        aS[0]=__float_as_uint(Ss[row*36+col]);     aS[1]=__float_as_uint(Ss[(row+8)*36+col]);
        aS[2]=__float_as_uint(Ss[row*36+col+4]);   aS[3]=__float_as_uint(Ss[(row+8)*36+col+4]);
        #pragma unroll
        for (int nt = 0; nt < 8; nt++) {
            int n = warpN*64 + nt*8 + g;
            uint32_t br0 = __float_as_uint(XR[(ks*8+tig)*132 + n]);
            uint32_t br1 = __float_as_uint(XR[(ks*8+tig+4)*132 + n]);
            uint32_t bi0 = __float_as_uint(XI[(ks*8+tig)*132 + n]);
            uint32_t bi1 = __float_as_uint(XI[(ks*8+tig+4)*132 + n]);
            mma1688(co[nt], aC, br0, br1);
            mma1688(co[nt], aS, bi0, bi1);
        }
    }

    int w0 = warpM*16 + g;
    size_t ob = (size_t)bh*WW*CCH + c0;
    #pragma unroll
    for (int nt = 0; nt < 8; nt++) {
        int n2 = warpN*64 + nt*8 + 2*tig;
        *(float2*)&out[ob + (size_t)w0*CCH + n2] = make_float2(co[nt][0], co[nt][1]);
        if (warpM < 3)
            *(float2*)&out[ob + (size_t)(w0+8)*CCH + n2] = make_float2(co[nt][2], co[nt][3]);
    }
}

// ========== MLP GEMM via mma.sync tf32 (unchanged from R3) ===================
#define GA0 0
#define GA1 4608
#define GB0 9216
#define GB1 13824
#define GBIAS 18432
#define GEMM_SMEM ((18432 + 128)*4)

template<int LAYER>
__device__ __forceinline__ void gload(int blk, int p0, int n0, int kc,
                                      uint32_t aS, uint32_t bS, int t)
{
    const float* inR = (LAYER==1) ? g_Br : g_Ar;
    const float* inI = (LAYER==1) ? g_Bi : g_Ai;
    const float* Wt  = ((LAYER==1) ? g_W1 : g_W2) + (size_t)blk*384*384;
    const float* src = (kc < 6) ? inR : inI;
    int koff = blk*192 + ((kc < 6) ? kc*32 : (kc-6)*32);
    int row = t >> 3, q = t & 7;
    #pragma unroll
    for (int i = 0; i < 4; i++) {
        int r = row + i*32;
        CP_ASYNC16(aS + (uint32_t)(r*36 + q*4)*4, &src[(size_t)(p0+r)*CCH + koff + q*4]);
    }
    int kb = kc*32;
    #pragma unroll
    for (int i = 0; i < 4; i++) {
        int r = row + i*32;
        CP_ASYNC16(bS + (uint32_t)(r*36 + q*4)*4, &Wt[(size_t)(n0+r)*384 + kb + q*4]);
    }
}

template<int LAYER>
__global__ void __launch_bounds__(256, 2) gemmM_k()
{
    extern __shared__ float sm[];
    uint32_t smem_base = smem_u32(sm);
    int t = threadIdx.x;
    int wid = t >> 5, lane = t & 31;
    int g = lane >> 2, tig = lane & 3;
    int warpM = wid & 3, warpN = wid >> 2;
    int p0  = blockIdx.x * 128;
    int n0  = blockIdx.y * 128;
    int blk = blockIdx.z;

    float*       outR = (LAYER==1) ? g_Ar : g_Br;
    float*       outI = (LAYER==1) ? g_Ai : g_Bi;
    const float* bias = ((LAYER==1) ? g_b1 : g_b2) + blk*192*2;

    for (int i = t; i < 128; i += 256) sm[GBIAS + i] = bias[n0 + i];

    float c[2][8][4];
    #pragma unroll
    for (int mt=0;mt<2;mt++)
        #pragma unroll
        for (int nt=0;nt<8;nt++)
            #pragma unroll
            for (int j=0;j<4;j++) c[mt][nt][j] = 0.f;

    gload<LAYER>(blk, p0, n0, 0, smem_base + GA0*4, smem_base + GB0*4, t);
    CP_COMMIT();

    #pragma unroll 1
    for (int kc = 0; kc < 12; kc++) {
        int b = kc & 1;
        if (kc + 1 < 12) {
            gload<LAYER>(blk, p0, n0, kc+1,
                         smem_base + (b ? GA0 : GA1)*4,
                         smem_base + (b ? GB0 : GB1)*4, t);
            CP_COMMIT();
            CP_WAIT(1);
        } else {
            CP_WAIT(0);
        }
        __syncthreads();

        const float* As = sm + (b ? GA1 : GA0);
        const float* Bs = sm + (b ? GB1 : GB0);
        #pragma unroll
        for (int ks = 0; ks < 4; ks++) {
            uint32_t a[2][4];
            #pragma unroll
            for (int mt = 0; mt < 2; mt++) {
                int r = warpM*32 + mt*16 + g;
                int col = ks*8 + tig;
                a[mt][0] = __float_as_uint(As[r*36 + col]);
                a[mt][1] = __float_as_uint(As[(r+8)*36 + col]);
                a[mt][2] = __float_as_uint(As[r*36 + col + 4]);
                a[mt][3] = __float_as_uint(As[(r+8)*36 + col + 4]);
            }
            #pragma unroll
            for (int nt = 0; nt < 8; nt++) {
                int n = warpN*64 + nt*8 + g;
                uint32_t b0 = __float_as_uint(Bs[n*36 + ks*8 + tig]);
                uint32_t b1 = __float_as_uint(Bs[n*36 + ks*8 + tig + 4]);
                mma1688(c[0][nt], a[0], b0, b1);
                mma1688(c[1][nt], a[1], b0, b1);
            }
        }
        __syncthreads();
    }

    #pragma unroll
    for (int mt = 0; mt < 2; mt++) {
        #pragma unroll
        for (int rr = 0; rr < 2; rr++) {
            int r = p0 + warpM*32 + mt*16 + rr*8 + g;
            size_t rowoff = (size_t)r*CCH + blk*192;
            #pragma unroll
            for (int nt = 0; nt < 8; nt++) {
                int kl = warpN*64 + nt*8 + 2*tig;
                int ko = n0 + kl;
                float v0 = c[mt][nt][rr*2+0] + sm[GBIAS + kl];
                float v1 = c[mt][nt][rr*2+1] + sm[GBIAS + kl + 1];
                if (LAYER == 1) {
                    v0 = to_tf32(fmaxf(v0, 0.f));
                    v1 = to_tf32(fmaxf(v1, 0.f));
                } else {
                    v0 = (v0 >  SSHRINK) ? v0-SSHRINK : ((v0 < -SSHRINK) ? v0+SSHRINK : 0.f);
                    v1 = (v1 >  SSHRINK) ? v1-SSHRINK : ((v1 < -SSHRINK) ? v1+SSHRINK : 0.f);
                }
                float* dst = (ko < 192) ? outR : outI;
                int kr = (ko < 192) ? ko : ko - 192;
                *(float2*)&dst[rowoff + kr] = make_float2(v0, v1);
            }
        }
    }
}

// ---------------- launch ------------------------------------------------------
extern "C" void kernel_launch(void* const* d_in, const int* in_sizes, int n_in,
                              void* d_out, int out_size)
{
    const float* x  = (const float*)d_in[0];
    const float* w1 = (const float*)d_in[1];
    const float* b1 = (const float*)d_in[2];
    const float* w2 = (const float*)d_in[3];
    const float* b2 = (const float*)d_in[4];
    float* out = (float*)d_out;

    cudaFuncSetAttribute((const void*)rfftWT_k,   cudaFuncAttributeMaxDynamicSharedMemorySize, RW_TOT);
    cudaFuncSetAttribute((const void*)fftHT_k<0>, cudaFuncAttributeMaxDynamicSharedMemorySize, FH_TOT);
    cudaFuncSetAttribute((const void*)fftHT_k<1>, cudaFuncAttributeMaxDynamicSharedMemorySize, FH_TOT);
    cudaFuncSetAttribute((const void*)irfftWT_k,  cudaFuncAttributeMaxDynamicSharedMemorySize, IW_TOT);
    cudaFuncSetAttribute((const void*)gemmM_k<1>, cudaFuncAttributeMaxDynamicSharedMemorySize, GEMM_SMEM);
    cudaFuncSetAttribute((const void*)gemmM_k<2>, cudaFuncAttributeMaxDynamicSharedMemorySize, GEMM_SMEM);

    init_k<<<512, 256>>>(w1, b1, w2, b2);
    rfftWT_k<<<dim3(BB*HH, 6), 256, RW_TOT>>>(x);
    fftHT_k<0><<<dim3(BB, 174), 256, FH_TOT>>>();
    gemmM_k<1><<<dim3(406, 3, NBLK), 256, GEMM_SMEM>>>();
    gemmM_k<2><<<dim3(406, 3, NBLK), 256, GEMM_SMEM>>>();
    fftHT_k<1><<<dim3(BB, 174), 256, FH_TOT>>>();
    irfftWT_k<<<dim3(BB*HH, 6), 256, IW_TOT>>>(out);
}